// round 2
// baseline (speedup 1.0000x reference)
#include <cuda_runtime.h>

#define MAX_GRID 4096
__device__ float g_partial_ce[MAX_GRID];
__device__ float g_partial_rl[MAX_GRID];

__device__ __forceinline__ float smooth_l1(float d) {
    float ad = fabsf(d);
    return (ad < 1.0f) ? 0.5f * d * d : ad - 0.5f;
}

__global__ void __launch_bounds__(256)
mbl_reduce_kernel(const float2* __restrict__ cout,
                  const float4* __restrict__ rout,
                  const int* __restrict__ cls,
                  const float4* __restrict__ regt,
                  int n)
{
    float ce_sum = 0.0f;
    float rl_sum = 0.0f;

    const int stride = gridDim.x * blockDim.x;
    for (int i = blockIdx.x * blockDim.x + threadIdx.x; i < n; i += stride) {
        int l = cls[i];
        float2 c = cout[i];
        float4 r = rout[i];
        float4 t = regt[i];

        // classification CE for selected (label 0 or 1)
        if (l <= 1) {
            float m  = fmaxf(c.x, c.y);
            float d  = fabsf(c.x - c.y);
            float lse = m + __logf(1.0f + __expf(-d));
            float logit = (l == 1) ? c.y : c.x;
            ce_sum += lse - logit;
        }
        // regression smooth-L1 for positive (label 1)
        if (l == 1) {
            float s = smooth_l1(r.x - t.x)
                    + smooth_l1(r.y - t.y)
                    + smooth_l1(r.z - t.z)
                    + smooth_l1(r.w - t.w);
            rl_sum += s * 0.25f;
        }
    }

    // warp reduce
    #pragma unroll
    for (int off = 16; off > 0; off >>= 1) {
        ce_sum += __shfl_down_sync(0xFFFFFFFF, ce_sum, off);
        rl_sum += __shfl_down_sync(0xFFFFFFFF, rl_sum, off);
    }

    __shared__ float s_ce[8];
    __shared__ float s_rl[8];
    int lane = threadIdx.x & 31;
    int wid  = threadIdx.x >> 5;
    if (lane == 0) { s_ce[wid] = ce_sum; s_rl[wid] = rl_sum; }
    __syncthreads();

    if (wid == 0) {
        ce_sum = (lane < 8) ? s_ce[lane] : 0.0f;
        rl_sum = (lane < 8) ? s_rl[lane] : 0.0f;
        #pragma unroll
        for (int off = 4; off > 0; off >>= 1) {
            ce_sum += __shfl_down_sync(0xFFFFFFFF, ce_sum, off);
            rl_sum += __shfl_down_sync(0xFFFFFFFF, rl_sum, off);
        }
        if (lane == 0) {
            g_partial_ce[blockIdx.x] = ce_sum;
            g_partial_rl[blockIdx.x] = rl_sum;
        }
    }
}

__global__ void __launch_bounds__(256)
mbl_final_kernel(float* __restrict__ out, int nblocks)
{
    float ce = 0.0f, rl = 0.0f;
    for (int i = threadIdx.x; i < nblocks; i += 256) {
        ce += g_partial_ce[i];
        rl += g_partial_rl[i];
    }
    #pragma unroll
    for (int off = 16; off > 0; off >>= 1) {
        ce += __shfl_down_sync(0xFFFFFFFF, ce, off);
        rl += __shfl_down_sync(0xFFFFFFFF, rl, off);
    }
    __shared__ float s_ce[8];
    __shared__ float s_rl[8];
    int lane = threadIdx.x & 31;
    int wid  = threadIdx.x >> 5;
    if (lane == 0) { s_ce[wid] = ce; s_rl[wid] = rl; }
    __syncthreads();
    if (threadIdx.x == 0) {
        float tce = 0.0f, trl = 0.0f;
        #pragma unroll
        for (int w = 0; w < 8; w++) { tce += s_ce[w]; trl += s_rl[w]; }
        float closs = tce * (1.0f / 64.0f);
        float rloss = trl * (1.0f / 16.0f);
        out[0] = closs;
        out[1] = rloss;
        out[2] = closs + 10.0f * rloss;
    }
}

extern "C" void kernel_launch(void* const* d_in, const int* in_sizes, int n_in,
                              void* d_out, int out_size)
{
    const float2* cout = (const float2*)d_in[0];
    const float4* rout = (const float4*)d_in[1];
    const int*    cls  = (const int*)d_in[2];
    const float4* regt = (const float4*)d_in[3];
    float* out = (float*)d_out;

    int n = in_sizes[2];           // cls_t element count == N
    const int BLOCK = 256;
    int grid = 148 * 8;            // 1184 blocks, ~7 elems/thread
    if (grid > MAX_GRID) grid = MAX_GRID;

    mbl_reduce_kernel<<<grid, BLOCK>>>(cout, rout, cls, regt, n);
    mbl_final_kernel<<<1, BLOCK>>>(out, grid);
}

// round 3
// speedup vs baseline: 1.0525x; 1.0525x over previous
#include <cuda_runtime.h>

#define MAX_GRID 4096
__device__ float g_partial_ce[MAX_GRID];
__device__ float g_partial_rl[MAX_GRID];
__device__ unsigned int g_ticket = 0;

__device__ __forceinline__ float smooth_l1(float d) {
    float ad = fabsf(d);
    return (ad < 1.0f) ? 0.5f * d * d : ad - 0.5f;
}

__global__ void __launch_bounds__(256)
mbl_fused_kernel(const float2* __restrict__ cout,
                 const float4* __restrict__ rout,
                 const int* __restrict__ cls,
                 const float4* __restrict__ regt,
                 float* __restrict__ out,
                 int n)
{
    float ce_sum = 0.0f;
    float rl_sum = 0.0f;

    const int stride = gridDim.x * blockDim.x;
    for (int i = blockIdx.x * blockDim.x + threadIdx.x; i < n; i += stride) {
        int l = cls[i];
        float2 c = cout[i];
        float4 r = rout[i];
        float4 t = regt[i];

        if (l <= 1) {
            float m  = fmaxf(c.x, c.y);
            float d  = fabsf(c.x - c.y);
            float lse = m + __logf(1.0f + __expf(-d));
            float logit = (l == 1) ? c.y : c.x;
            ce_sum += lse - logit;
        }
        if (l == 1) {
            float s = smooth_l1(r.x - t.x)
                    + smooth_l1(r.y - t.y)
                    + smooth_l1(r.z - t.z)
                    + smooth_l1(r.w - t.w);
            rl_sum += s * 0.25f;
        }
    }

    // intra-block reduction
    #pragma unroll
    for (int off = 16; off > 0; off >>= 1) {
        ce_sum += __shfl_down_sync(0xFFFFFFFF, ce_sum, off);
        rl_sum += __shfl_down_sync(0xFFFFFFFF, rl_sum, off);
    }

    __shared__ float s_ce[8];
    __shared__ float s_rl[8];
    __shared__ bool s_last;
    int lane = threadIdx.x & 31;
    int wid  = threadIdx.x >> 5;
    if (lane == 0) { s_ce[wid] = ce_sum; s_rl[wid] = rl_sum; }
    __syncthreads();

    if (threadIdx.x == 0) {
        float tce = 0.0f, trl = 0.0f;
        #pragma unroll
        for (int w = 0; w < 8; w++) { tce += s_ce[w]; trl += s_rl[w]; }
        g_partial_ce[blockIdx.x] = tce;
        g_partial_rl[blockIdx.x] = trl;
        __threadfence();
        unsigned int t = atomicAdd(&g_ticket, 1u);
        s_last = (t == gridDim.x - 1);
    }
    __syncthreads();

    // last block to arrive performs the final reduction
    if (s_last) {
        float ce = 0.0f, rl = 0.0f;
        for (int i = threadIdx.x; i < gridDim.x; i += 256) {
            ce += g_partial_ce[i];
            rl += g_partial_rl[i];
        }
        #pragma unroll
        for (int off = 16; off > 0; off >>= 1) {
            ce += __shfl_down_sync(0xFFFFFFFF, ce, off);
            rl += __shfl_down_sync(0xFFFFFFFF, rl, off);
        }
        if (lane == 0) { s_ce[wid] = ce; s_rl[wid] = rl; }
        __syncthreads();
        if (threadIdx.x == 0) {
            float tce = 0.0f, trl = 0.0f;
            #pragma unroll
            for (int w = 0; w < 8; w++) { tce += s_ce[w]; trl += s_rl[w]; }
            float closs = tce * (1.0f / 64.0f);
            float rloss = trl * (1.0f / 16.0f);
            out[0] = closs;
            out[1] = rloss;
            out[2] = closs + 10.0f * rloss;
            g_ticket = 0;   // reset for next (graph-replayed) launch
        }
    }
}

extern "C" void kernel_launch(void* const* d_in, const int* in_sizes, int n_in,
                              void* d_out, int out_size)
{
    const float2* cout = (const float2*)d_in[0];
    const float4* rout = (const float4*)d_in[1];
    const int*    cls  = (const int*)d_in[2];
    const float4* regt = (const float4*)d_in[3];
    float* out = (float*)d_out;

    int n = in_sizes[2];
    const int BLOCK = 256;
    int grid = 148 * 8;
    if (grid > MAX_GRID) grid = MAX_GRID;

    mbl_fused_kernel<<<grid, BLOCK>>>(cout, rout, cls, regt, out, n);
}

// round 4
// speedup vs baseline: 1.0551x; 1.0025x over previous
#include <cuda_runtime.h>

#define MAX_GRID 4096
__device__ float g_partial_ce[MAX_GRID];
__device__ float g_partial_rl[MAX_GRID];
__device__ unsigned int g_ticket = 0;

__device__ __forceinline__ float smooth_l1(float d) {
    float ad = fabsf(d);
    return (ad < 1.0f) ? 0.5f * d * d : ad - 0.5f;
}

// per-element math, branchless
__device__ __forceinline__ void accum_one(int l, float cx, float cy,
                                          const float4& r, const float4& t,
                                          float& ce_sum, float& rl_sum)
{
    // CE: selected if l <= 1
    float m   = fmaxf(cx, cy);
    float d   = fabsf(cx - cy);
    float lse = m + __logf(1.0f + __expf(-d));
    float logit = (l == 1) ? cy : cx;
    float sel  = (l <= 1) ? 1.0f : 0.0f;
    ce_sum = fmaf(sel, lse - logit, ce_sum);

    // smooth L1: only if l == 1
    float s = smooth_l1(r.x - t.x)
            + smooth_l1(r.y - t.y)
            + smooth_l1(r.z - t.z)
            + smooth_l1(r.w - t.w);
    float pos = (l == 1) ? 0.25f : 0.0f;
    rl_sum = fmaf(pos, s, rl_sum);
}

__global__ void __launch_bounds__(256)
mbl_fused_kernel(const float4* __restrict__ cout2,   // 2 anchors per float4
                 const float4* __restrict__ rout,
                 const int2*   __restrict__ cls2,    // 2 labels per int2
                 const float4* __restrict__ regt,
                 float* __restrict__ out,
                 int n)                                // n = number of PAIRS
{
    float ce_sum = 0.0f;
    float rl_sum = 0.0f;

    const int stride = gridDim.x * blockDim.x;
    for (int i = blockIdx.x * blockDim.x + threadIdx.x; i < n; i += stride) {
        int2   l2 = cls2[i];
        float4 c  = cout2[i];
        float4 r0 = rout[2 * i];
        float4 r1 = rout[2 * i + 1];
        float4 t0 = regt[2 * i];
        float4 t1 = regt[2 * i + 1];

        accum_one(l2.x, c.x, c.y, r0, t0, ce_sum, rl_sum);
        accum_one(l2.y, c.z, c.w, r1, t1, ce_sum, rl_sum);
    }

    // intra-block reduction
    #pragma unroll
    for (int off = 16; off > 0; off >>= 1) {
        ce_sum += __shfl_down_sync(0xFFFFFFFF, ce_sum, off);
        rl_sum += __shfl_down_sync(0xFFFFFFFF, rl_sum, off);
    }

    __shared__ float s_ce[8];
    __shared__ float s_rl[8];
    __shared__ bool s_last;
    int lane = threadIdx.x & 31;
    int wid  = threadIdx.x >> 5;
    if (lane == 0) { s_ce[wid] = ce_sum; s_rl[wid] = rl_sum; }
    __syncthreads();

    if (threadIdx.x == 0) {
        float tce = 0.0f, trl = 0.0f;
        #pragma unroll
        for (int w = 0; w < 8; w++) { tce += s_ce[w]; trl += s_rl[w]; }
        g_partial_ce[blockIdx.x] = tce;
        g_partial_rl[blockIdx.x] = trl;
        __threadfence();
        unsigned int t = atomicAdd(&g_ticket, 1u);
        s_last = (t == gridDim.x - 1);
    }
    __syncthreads();

    if (s_last) {
        float ce = 0.0f, rl = 0.0f;
        for (int i = threadIdx.x; i < gridDim.x; i += 256) {
            ce += g_partial_ce[i];
            rl += g_partial_rl[i];
        }
        #pragma unroll
        for (int off = 16; off > 0; off >>= 1) {
            ce += __shfl_down_sync(0xFFFFFFFF, ce, off);
            rl += __shfl_down_sync(0xFFFFFFFF, rl, off);
        }
        if (lane == 0) { s_ce[wid] = ce; s_rl[wid] = rl; }
        __syncthreads();
        if (threadIdx.x == 0) {
            float tce = 0.0f, trl = 0.0f;
            #pragma unroll
            for (int w = 0; w < 8; w++) { tce += s_ce[w]; trl += s_rl[w]; }
            float closs = tce * (1.0f / 64.0f);
            float rloss = trl * (1.0f / 16.0f);
            out[0] = closs;
            out[1] = rloss;
            out[2] = closs + 10.0f * rloss;
            g_ticket = 0;   // reset for next graph replay
        }
    }
}

extern "C" void kernel_launch(void* const* d_in, const int* in_sizes, int n_in,
                              void* d_out, int out_size)
{
    const float4* cout2 = (const float4*)d_in[0];
    const float4* rout  = (const float4*)d_in[1];
    const int2*   cls2  = (const int2*)d_in[2];
    const float4* regt  = (const float4*)d_in[3];
    float* out = (float*)d_out;

    int n_elems = in_sizes[2];     // N = 2,000,000 (even)
    int n_pairs = n_elems >> 1;
    const int BLOCK = 256;
    int grid = 148 * 8;
    if (grid > MAX_GRID) grid = MAX_GRID;

    mbl_fused_kernel<<<grid, BLOCK>>>(cout2, rout, cls2, regt, out, n_pairs);
}